// round 3
// baseline (speedup 1.0000x reference)
#include <cuda_runtime.h>

typedef unsigned long long ull;

// ---- packed f32x2 helpers (Blackwell FFMA2 only reachable via PTX) ----
__device__ __forceinline__ ull fma2(ull a, ull b, ull c) {
    ull d;
    asm("fma.rn.f32x2 %0, %1, %2, %3;" : "=l"(d) : "l"(a), "l"(b), "l"(c));
    return d;
}
__device__ __forceinline__ ull pk2(float lo, float hi) {
    ull r;
    asm("mov.b64 %0, {%1, %2};" : "=l"(r) : "f"(lo), "f"(hi));
    return r;
}
__device__ __forceinline__ void upk2(ull v, float& lo, float& hi) {
    asm("mov.b64 {%0, %1}, %2;" : "=f"(lo), "=f"(hi) : "l"(v));
}
__device__ __forceinline__ float elu1(float v) {
    // v>0: max=v, exp(0)-1=0 -> v ; v<=0: 0 + exp(v)-1
    float e = __expf(fminf(v, 0.0f)) - 1.0f;
    return fmaxf(v, 0.0f) + e;
}
__device__ __forceinline__ ull elu2(ull v) {
    float a, b; upk2(v, a, b);
    return pk2(elu1(a), elu1(b));
}

static constexpr int T_STEPS = 64;
static constexpr int NSIDE = 256;
static constexpr int NPTS = NSIDE * NSIDE;   // 65536
static constexpr int HID = 32;

// Each thread computes 4 consecutive points (same row, same t) as 2 f32x2 pairs.
// Weights live in SMEM pre-duplicated as {w,w} 64-bit values so an LDS.64
// broadcast directly yields the FFMA2 multiplier operand.
__global__ __launch_bounds__(256, 1)
void mlpconv_kernel(const float* __restrict__ x,
                    const float* __restrict__ W0, const float* __restrict__ b0,
                    const float* __restrict__ W1, const float* __restrict__ b1,
                    const float* __restrict__ W2, const float* __restrict__ b2,
                    float* __restrict__ out) {
    __shared__ ull sW0[5 * HID];
    __shared__ ull sB0[HID];
    __shared__ ull sW1[HID * HID];
    __shared__ ull sB1[HID];
    __shared__ ull sW2[HID];
    __shared__ float sB2;

    const int tid = threadIdx.x;
    // stage weights (duplicated into both f32 halves)
    for (int i0 = tid; i0 < 5 * HID; i0 += 256) {
        unsigned u = __float_as_uint(W0[i0]);
        sW0[i0] = (ull)u | ((ull)u << 32);
    }
    for (int i0 = tid; i0 < HID * HID; i0 += 256) {
        unsigned u = __float_as_uint(W1[i0]);
        sW1[i0] = (ull)u | ((ull)u << 32);
    }
    if (tid < HID) {
        unsigned u0 = __float_as_uint(b0[tid]);
        unsigned u1 = __float_as_uint(b1[tid]);
        unsigned u2 = __float_as_uint(W2[tid]);
        sB0[tid] = (ull)u0 | ((ull)u0 << 32);
        sB1[tid] = (ull)u1 | ((ull)u1 << 32);
        sW2[tid] = (ull)u2 | ((ull)u2 << 32);
    }
    if (tid == 0) sB2 = b2[0];
    __syncthreads();

    const int gid = blockIdx.x * 256 + tid;
    const int base = gid * 4;                 // < 4194304, fits in int
    const int t = base >> 16;                 // / NPTS
    const int p = base & (NPTS - 1);
    const float* xt = x + ((size_t)t << 16);
    const int i = p >> 8;
    const int j = p & 255;

    // Stencil (reference's exact wrap semantics):
    //  l  = x[(q-1)   & (N-1)]   (global flat wrap)
    //  l2 = x[(q-256) & (N-1)]
    //  c  = x[q]
    //  r  = x[i*256 + ((jq+1)&255)]  (row-periodic)
    //  r2 = x[(q+256) & (N-1)]
    const float4 c4 = *reinterpret_cast<const float4*>(xt + p);
    const float4 u4 = *reinterpret_cast<const float4*>(xt + ((p - NSIDE) & (NPTS - 1)));
    const float4 d4 = *reinterpret_cast<const float4*>(xt + ((p + NSIDE) & (NPTS - 1)));
    const float lE = xt[(p - 1) & (NPTS - 1)];
    const float rE = xt[(i << 8) | ((j + 4) & 255)];

    // pair0 = points (0,1), pair1 = points (2,3)
    ull pxl[2] = { pk2(lE,   c4.x), pk2(c4.y, c4.z) };
    ull pxu[2] = { pk2(u4.x, u4.y), pk2(u4.z, u4.w) };
    ull pxc[2] = { pk2(c4.x, c4.y), pk2(c4.z, c4.w) };
    ull pxr[2] = { pk2(c4.y, c4.z), pk2(c4.w, rE)   };
    ull pxd[2] = { pk2(d4.x, d4.y), pk2(d4.z, d4.w) };

    // ---- layer 0: [5] -> [32], ELU ----
    ull h0a[HID], h0b[HID];
#pragma unroll
    for (int jj = 0; jj < HID; jj++) {
        ull a = sB0[jj];
        ull b = a;
        ull w;
        w = sW0[0 * HID + jj]; a = fma2(pxl[0], w, a); b = fma2(pxl[1], w, b);
        w = sW0[1 * HID + jj]; a = fma2(pxu[0], w, a); b = fma2(pxu[1], w, b);
        w = sW0[2 * HID + jj]; a = fma2(pxc[0], w, a); b = fma2(pxc[1], w, b);
        w = sW0[3 * HID + jj]; a = fma2(pxr[0], w, a); b = fma2(pxr[1], w, b);
        w = sW0[4 * HID + jj]; a = fma2(pxd[0], w, a); b = fma2(pxd[1], w, b);
        h0a[jj] = elu2(a);
        h0b[jj] = elu2(b);
    }

    // ---- layer 1: [32] -> [32], ELU, fused with layer 2 accumulation ----
    ull oa = pk2(sB2, sB2);
    ull ob = oa;
#pragma unroll 4
    for (int jj = 0; jj < HID; jj++) {
        ull a = sB1[jj];
        ull b = a;
#pragma unroll
        for (int cc = 0; cc < HID; cc++) {
            ull w = sW1[cc * HID + jj];
            a = fma2(h0a[cc], w, a);
            b = fma2(h0b[cc], w, b);
        }
        a = elu2(a);
        b = elu2(b);
        ull w2 = sW2[jj];
        oa = fma2(a, w2, oa);
        ob = fma2(b, w2, ob);
    }

    float o0, o1, o2, o3;
    upk2(oa, o0, o1);
    upk2(ob, o2, o3);
    *reinterpret_cast<float4*>(out + base) = make_float4(o0, o1, o2, o3);
}

extern "C" void kernel_launch(void* const* d_in, const int* in_sizes, int n_in,
                              void* d_out, int out_size) {
    const float* x  = (const float*)d_in[0];
    const float* W0 = (const float*)d_in[1];
    const float* b0 = (const float*)d_in[2];
    const float* W1 = (const float*)d_in[3];
    const float* b1 = (const float*)d_in[4];
    const float* W2 = (const float*)d_in[5];
    const float* b2 = (const float*)d_in[6];
    float* out = (float*)d_out;

    const int total = T_STEPS * NPTS;       // 4194304 points
    const int threads = total / 4;          // 4 points per thread
    mlpconv_kernel<<<threads / 256, 256>>>(x, W0, b0, W1, b1, W2, b2, out);
}

// round 4
// speedup vs baseline: 1.0132x; 1.0132x over previous
#include <cuda_runtime.h>

typedef unsigned long long ull;

// ---- packed f32x2 helpers (Blackwell FFMA2 only reachable via PTX) ----
__device__ __forceinline__ ull fma2(ull a, ull b, ull c) {
    ull d;
    asm("fma.rn.f32x2 %0, %1, %2, %3;" : "=l"(d) : "l"(a), "l"(b), "l"(c));
    return d;
}
__device__ __forceinline__ ull pk2(float lo, float hi) {
    ull r;
    asm("mov.b64 %0, {%1, %2};" : "=l"(r) : "f"(lo), "f"(hi));
    return r;
}
__device__ __forceinline__ void upk2(ull v, float& lo, float& hi) {
    asm("mov.b64 {%0, %1}, %2;" : "=f"(lo), "=f"(hi) : "l"(v));
}
// g(v) = elu(v) + 1 = max(v,0) + exp(min(v,0)); the "-1" is folded into the
// next layer's bias (b1' = b1 - sum_c W1[c][:], b2' = b2 - sum_j W2[j]).
__device__ __forceinline__ float g1(float v) {
    return fmaxf(v, 0.0f) + __expf(fminf(v, 0.0f));
}
__device__ __forceinline__ ull g2(ull v) {
    float a, b; upk2(v, a, b);
    return pk2(g1(a), g1(b));
}

static constexpr int T_STEPS = 64;
static constexpr int NSIDE = 256;
static constexpr int NPTS = NSIDE * NSIDE;   // 65536
static constexpr int HID = 32;

// 4 consecutive points per thread as 2 f32x2 pairs. Weights in SMEM as
// duplicated {w,w} u64, W1 TRANSPOSED to [jj][cc] so LDS.128 pulls two
// consecutive-cc weights per instruction (halves shared-load issue count).
__global__ __launch_bounds__(256, 1)
void mlpconv_kernel(const float* __restrict__ x,
                    const float* __restrict__ W0, const float* __restrict__ b0,
                    const float* __restrict__ W1, const float* __restrict__ b1,
                    const float* __restrict__ W2, const float* __restrict__ b2,
                    float* __restrict__ out) {
    // sW0r[jj][0..4] = dup(W0[c][jj]), [5] = dup(b0[jj]), rows padded to 8 (16B aligned)
    __shared__ __align__(16) ull sW0r[HID * 8];
    // sW1t[jj*32+cc] = dup(W1[cc][jj])
    __shared__ __align__(16) ull sW1t[HID * HID];
    __shared__ ull sB1[HID];      // dup(b1[jj] - sum_c W1[c][jj])
    __shared__ ull sW2[HID];      // dup(W2[jj])
    __shared__ float sB2;         // b2 - sum_j W2[j]

    const int tid = threadIdx.x;

    // ---- stage weights ----
    for (int i0 = tid; i0 < HID * HID; i0 += 256) {
        // i0 = jj*32 + cc  ->  W1[cc*32 + jj]
        unsigned u = __float_as_uint(W1[((i0 & 31) << 5) | (i0 >> 5)]);
        sW1t[i0] = (ull)u | ((ull)u << 32);
    }
    for (int i0 = tid; i0 < HID * 8; i0 += 256) {
        int jj = i0 >> 3, c = i0 & 7;
        float v = 0.0f;
        if (c < 5)       v = W0[c * HID + jj];
        else if (c == 5) v = b0[jj];
        unsigned u = __float_as_uint(v);
        sW0r[i0] = (ull)u | ((ull)u << 32);
    }
    if (tid < HID) {
        float s = 0.0f;
        for (int c = 0; c < HID; c++) s += W1[c * HID + tid];   // coalesced across tid
        unsigned u1 = __float_as_uint(b1[tid] - s);
        unsigned u2 = __float_as_uint(W2[tid]);
        sB1[tid] = (ull)u1 | ((ull)u1 << 32);
        sW2[tid] = (ull)u2 | ((ull)u2 << 32);
    }
    if (tid == 0) {
        float s = 0.0f;
        for (int jj = 0; jj < HID; jj++) s += W2[jj];
        sB2 = b2[0] - s;
    }
    __syncthreads();

    const int gid = blockIdx.x * 256 + tid;
    const int base = gid * 4;
    const int t = base >> 16;
    const int p = base & (NPTS - 1);
    const float* xt = x + ((size_t)t << 16);
    const int i = p >> 8;
    const int j = p & 255;

    // Stencil (reference's exact wrap semantics)
    const float4 c4 = *reinterpret_cast<const float4*>(xt + p);
    const float4 u4 = *reinterpret_cast<const float4*>(xt + ((p - NSIDE) & (NPTS - 1)));
    const float4 d4 = *reinterpret_cast<const float4*>(xt + ((p + NSIDE) & (NPTS - 1)));
    const float lE = xt[(p - 1) & (NPTS - 1)];
    const float rE = xt[(i << 8) | ((j + 4) & 255)];

    // pair0 = points (0,1), pair1 = points (2,3); order: l, l2(up), c, r, r2(down)
    ull px0[5] = { pk2(lE,   c4.x), pk2(u4.x, u4.y), pk2(c4.x, c4.y),
                   pk2(c4.y, c4.z), pk2(d4.x, d4.y) };
    ull px1[5] = { pk2(c4.y, c4.z), pk2(u4.z, u4.w), pk2(c4.z, c4.w),
                   pk2(c4.w, rE),   pk2(d4.z, d4.w) };

    // ---- layer 0: [5] -> [32], g-activation ----
    ull h0a[HID], h0b[HID];
#pragma unroll
    for (int jj = 0; jj < HID; jj++) {
        const ulonglong2* row = reinterpret_cast<const ulonglong2*>(sW0r + jj * 8);
        ulonglong2 w01 = row[0];   // w0, w1
        ulonglong2 w23 = row[1];   // w2, w3
        ulonglong2 w4b = row[2];   // w4, b0
        ull a = w4b.y;
        ull b = a;
        a = fma2(px0[0], w01.x, a); b = fma2(px1[0], w01.x, b);
        a = fma2(px0[1], w01.y, a); b = fma2(px1[1], w01.y, b);
        a = fma2(px0[2], w23.x, a); b = fma2(px1[2], w23.x, b);
        a = fma2(px0[3], w23.y, a); b = fma2(px1[3], w23.y, b);
        a = fma2(px0[4], w4b.x, a); b = fma2(px1[4], w4b.x, b);
        h0a[jj] = g2(a);
        h0b[jj] = g2(b);
    }

    // ---- layer 1: [32] -> [32], g-activation, fused layer-2 accumulation ----
    ull oa = pk2(sB2, sB2);
    ull ob = oa;
#pragma unroll 4
    for (int jj = 0; jj < HID; jj++) {
        ull a = sB1[jj];
        ull b = a;
        const ulonglong2* row = reinterpret_cast<const ulonglong2*>(sW1t + jj * HID);
#pragma unroll
        for (int k = 0; k < HID / 2; k++) {
            ulonglong2 w = row[k];                 // weights for cc=2k, 2k+1
            a = fma2(h0a[2 * k],     w.x, a);
            b = fma2(h0b[2 * k],     w.x, b);
            a = fma2(h0a[2 * k + 1], w.y, a);
            b = fma2(h0b[2 * k + 1], w.y, b);
        }
        a = g2(a);
        b = g2(b);
        ull w2 = sW2[jj];
        oa = fma2(a, w2, oa);
        ob = fma2(b, w2, ob);
    }

    float o0, o1, o2, o3;
    upk2(oa, o0, o1);
    upk2(ob, o2, o3);
    *reinterpret_cast<float4*>(out + base) = make_float4(o0, o1, o2, o3);
}

extern "C" void kernel_launch(void* const* d_in, const int* in_sizes, int n_in,
                              void* d_out, int out_size) {
    const float* x  = (const float*)d_in[0];
    const float* W0 = (const float*)d_in[1];
    const float* b0 = (const float*)d_in[2];
    const float* W1 = (const float*)d_in[3];
    const float* b1 = (const float*)d_in[4];
    const float* W2 = (const float*)d_in[5];
    const float* b2 = (const float*)d_in[6];
    float* out = (float*)d_out;

    const int total = T_STEPS * NPTS;       // 4194304 points
    const int threads = total / 4;          // 4 points per thread
    mlpconv_kernel<<<threads / 256, 256>>>(x, W0, b0, W1, b1, W2, b2, out);
}

// round 5
// speedup vs baseline: 1.0539x; 1.0401x over previous
#include <cuda_runtime.h>

typedef unsigned long long ull;

// ---- packed f32x2 helpers (Blackwell FFMA2 only reachable via PTX) ----
__device__ __forceinline__ ull fma2(ull a, ull b, ull c) {
    ull d;
    asm("fma.rn.f32x2 %0, %1, %2, %3;" : "=l"(d) : "l"(a), "l"(b), "l"(c));
    return d;
}
__device__ __forceinline__ ull pk2(float lo, float hi) {
    ull r;
    asm("mov.b64 %0, {%1, %2};" : "=l"(r) : "f"(lo), "f"(hi));
    return r;
}
__device__ __forceinline__ void upk2(ull v, float& lo, float& hi) {
    asm("mov.b64 {%0, %1}, %2;" : "=f"(lo), "=f"(hi) : "l"(v));
}
// g(v) = elu(v) + 1 = max(v,0) + exp(min(v,0)); the "-1" is folded into the
// next layer's bias (b1' = b1 - sum_c W1[c][:], b2' = b2 - sum_j W2[j]).
__device__ __forceinline__ float g1(float v) {
    return fmaxf(v, 0.0f) + __expf(fminf(v, 0.0f));
}
__device__ __forceinline__ ull g2(ull v) {
    float a, b; upk2(v, a, b);
    return pk2(g1(a), g1(b));
}

static constexpr int T_STEPS = 64;
static constexpr int NSIDE = 256;
static constexpr int NPTS = NSIDE * NSIDE;   // 65536
static constexpr int HID = 32;
static constexpr int BLK = 128;              // smaller blocks -> finer occupancy quanta

// 4 consecutive points per thread as 2 f32x2 pairs. Weights in SMEM as
// duplicated {w,w} u64 so an LDS broadcast directly yields the FFMA2
// multiplier. Reg-capped to 168 so 3 blocks (12 warps) fit per SM.
__global__ __launch_bounds__(BLK, 3)
void mlpconv_kernel(const float* __restrict__ x,
                    const float* __restrict__ W0, const float* __restrict__ b0,
                    const float* __restrict__ W1, const float* __restrict__ b1,
                    const float* __restrict__ W2, const float* __restrict__ b2,
                    float* __restrict__ out) {
    // sW0r[jj][0..4] = dup(W0[c][jj]), [5] = dup(b0[jj]), rows padded to 8 (16B aligned)
    __shared__ __align__(16) ull sW0r[HID * 8];
    // sW1t[jj*32+cc] = dup(W1[cc][jj])
    __shared__ __align__(16) ull sW1t[HID * HID];
    __shared__ ull sB1[HID];      // dup(b1[jj] - sum_c W1[c][jj])
    __shared__ ull sW2[HID];      // dup(W2[jj])
    __shared__ float sB2;         // b2 - sum_j W2[j]

    const int tid = threadIdx.x;

    // ---- stage weights ----
    for (int i0 = tid; i0 < HID * HID; i0 += BLK) {
        // i0 = jj*32 + cc  ->  W1[cc*32 + jj]
        unsigned u = __float_as_uint(W1[((i0 & 31) << 5) | (i0 >> 5)]);
        sW1t[i0] = (ull)u | ((ull)u << 32);
    }
    for (int i0 = tid; i0 < HID * 8; i0 += BLK) {
        int jj = i0 >> 3, c = i0 & 7;
        float v = 0.0f;
        if (c < 5)       v = W0[c * HID + jj];
        else if (c == 5) v = b0[jj];
        unsigned u = __float_as_uint(v);
        sW0r[i0] = (ull)u | ((ull)u << 32);
    }
    if (tid < HID) {
        float s = 0.0f;
        for (int c = 0; c < HID; c++) s += W1[c * HID + tid];   // coalesced across tid
        unsigned u1 = __float_as_uint(b1[tid] - s);
        unsigned u2 = __float_as_uint(W2[tid]);
        sB1[tid] = (ull)u1 | ((ull)u1 << 32);
        sW2[tid] = (ull)u2 | ((ull)u2 << 32);
    }
    if (tid == 0) {
        float s = 0.0f;
        for (int jj = 0; jj < HID; jj++) s += W2[jj];
        sB2 = b2[0] - s;
    }
    __syncthreads();

    const int gid = blockIdx.x * BLK + tid;
    const int base = gid * 4;
    const int t = base >> 16;
    const int p = base & (NPTS - 1);
    const float* xt = x + ((size_t)t << 16);
    const int i = p >> 8;
    const int j = p & 255;

    // Stencil (reference's exact wrap semantics)
    const float4 c4 = *reinterpret_cast<const float4*>(xt + p);
    const float4 u4 = *reinterpret_cast<const float4*>(xt + ((p - NSIDE) & (NPTS - 1)));
    const float4 d4 = *reinterpret_cast<const float4*>(xt + ((p + NSIDE) & (NPTS - 1)));
    const float lE = xt[(p - 1) & (NPTS - 1)];
    const float rE = xt[(i << 8) | ((j + 4) & 255)];

    // pair0 = points (0,1), pair1 = points (2,3); order: l, l2(up), c, r, r2(down)
    ull px0[5] = { pk2(lE,   c4.x), pk2(u4.x, u4.y), pk2(c4.x, c4.y),
                   pk2(c4.y, c4.z), pk2(d4.x, d4.y) };
    ull px1[5] = { pk2(c4.y, c4.z), pk2(u4.z, u4.w), pk2(c4.z, c4.w),
                   pk2(c4.w, rE),   pk2(d4.z, d4.w) };

    // ---- layer 0: [5] -> [32], g-activation ----
    ull h0a[HID], h0b[HID];
#pragma unroll
    for (int jj = 0; jj < HID; jj++) {
        const ulonglong2* row = reinterpret_cast<const ulonglong2*>(sW0r + jj * 8);
        ulonglong2 w01 = row[0];   // w0, w1
        ulonglong2 w23 = row[1];   // w2, w3
        ulonglong2 w4b = row[2];   // w4, b0
        ull a = w4b.y;
        ull b = a;
        a = fma2(px0[0], w01.x, a); b = fma2(px1[0], w01.x, b);
        a = fma2(px0[1], w01.y, a); b = fma2(px1[1], w01.y, b);
        a = fma2(px0[2], w23.x, a); b = fma2(px1[2], w23.x, b);
        a = fma2(px0[3], w23.y, a); b = fma2(px1[3], w23.y, b);
        a = fma2(px0[4], w4b.x, a); b = fma2(px1[4], w4b.x, b);
        h0a[jj] = g2(a);
        h0b[jj] = g2(b);
    }

    // ---- layer 1: [32] -> [32], g-activation, fused layer-2 accumulation ----
    // unroll 2 over jj: enough ILP for 3 warps/SMSP without blowing the
    // 168-reg budget on hoisted weight batches.
    ull oa = pk2(sB2, sB2);
    ull ob = oa;
#pragma unroll 2
    for (int jj = 0; jj < HID; jj++) {
        ull a = sB1[jj];
        ull b = a;
        const ulonglong2* row = reinterpret_cast<const ulonglong2*>(sW1t + jj * HID);
#pragma unroll
        for (int k = 0; k < HID / 2; k++) {
            ulonglong2 w = row[k];                 // weights for cc=2k, 2k+1
            a = fma2(h0a[2 * k],     w.x, a);
            b = fma2(h0b[2 * k],     w.x, b);
            a = fma2(h0a[2 * k + 1], w.y, a);
            b = fma2(h0b[2 * k + 1], w.y, b);
        }
        a = g2(a);
        b = g2(b);
        ull w2 = sW2[jj];
        oa = fma2(a, w2, oa);
        ob = fma2(b, w2, ob);
    }

    float o0, o1, o2, o3;
    upk2(oa, o0, o1);
    upk2(ob, o2, o3);
    *reinterpret_cast<float4*>(out + base) = make_float4(o0, o1, o2, o3);
}

extern "C" void kernel_launch(void* const* d_in, const int* in_sizes, int n_in,
                              void* d_out, int out_size) {
    const float* x  = (const float*)d_in[0];
    const float* W0 = (const float*)d_in[1];
    const float* b0 = (const float*)d_in[2];
    const float* W1 = (const float*)d_in[3];
    const float* b1 = (const float*)d_in[4];
    const float* W2 = (const float*)d_in[5];
    const float* b2 = (const float*)d_in[6];
    float* out = (float*)d_out;

    const int total = T_STEPS * NPTS;       // 4194304 points
    const int threads = total / 4;          // 4 points per thread
    mlpconv_kernel<<<threads / BLK, BLK>>>(x, W0, b0, W1, b1, W2, b2, out);
}

// round 7
// speedup vs baseline: 1.0911x; 1.0353x over previous
#include <cuda_runtime.h>

typedef unsigned long long ull;

// ---- packed f32x2 helpers (Blackwell FFMA2 only reachable via PTX) ----
__device__ __forceinline__ ull fma2(ull a, ull b, ull c) {
    ull d;
    asm("fma.rn.f32x2 %0, %1, %2, %3;" : "=l"(d) : "l"(a), "l"(b), "l"(c));
    return d;
}
__device__ __forceinline__ ull pk2(float lo, float hi) {
    ull r;
    asm("mov.b64 %0, {%1, %2};" : "=l"(r) : "f"(lo), "f"(hi));
    return r;
}
__device__ __forceinline__ void upk2(ull v, float& lo, float& hi) {
    asm("mov.b64 {%0, %1}, %2;" : "=f"(lo), "=f"(hi) : "l"(v));
}
__device__ __forceinline__ float ex2f(float v) {
    float r;
    asm("ex2.approx.f32 %0, %1;" : "=f"(r) : "f"(v));
    return r;
}

// Weights feeding any activated layer are PRE-SCALED by log2(e) at staging,
// so the preactivation v' = log2e * v. Then
//   g(v) = elu(v) + 1 = max(v,0) + exp(min(v,0))
//        = max(v',0)*ln2 + ex2(min(v',0))
// (the "-1" is folded into the next layer's bias: b1' = b1 - sum_c W1[c][:],
//  b2' = b2 - sum_j W2[j]).  8 issue slots per pair: fmin x2, MUFU x2,
// fmax x2, FFMA x2 (no separate mul-by-log2e, no separate add).
__device__ __forceinline__ ull g2(ull v) {
    const float LN2 = 0.69314718055994530942f;
    float a, b; upk2(v, a, b);
    float ea = ex2f(fminf(a, 0.0f));
    float eb = ex2f(fminf(b, 0.0f));
    float ha = fmaf(fmaxf(a, 0.0f), LN2, ea);
    float hb = fmaf(fmaxf(b, 0.0f), LN2, eb);
    return pk2(ha, hb);
}

static constexpr int T_STEPS = 64;
static constexpr int NSIDE = 256;
static constexpr int NPTS = NSIDE * NSIDE;   // 65536
static constexpr int HID = 32;
static constexpr int BLK = 128;
static constexpr float LOG2E = 1.44269504088896340736f;

// 4 consecutive points per thread as 2 f32x2 pairs. Weights in SMEM as
// duplicated {w,w} u64 so an LDS broadcast directly yields the FFMA2
// multiplier. Reg-capped to 168 so 3 blocks (12 warps) fit per SM.
__global__ __launch_bounds__(BLK, 3)
void mlpconv_kernel(const float* __restrict__ x,
                    const float* __restrict__ W0, const float* __restrict__ b0,
                    const float* __restrict__ W1, const float* __restrict__ b1,
                    const float* __restrict__ W2, const float* __restrict__ b2,
                    float* __restrict__ out) {
    // sW0r[jj][0..4] = dup(log2e*W0[c][jj]), [5] = dup(log2e*b0[jj]), rows padded to 8
    __shared__ __align__(16) ull sW0r[HID * 8];
    // sW1t[jj*32+cc] = dup(log2e*W1[cc][jj])
    __shared__ __align__(16) ull sW1t[HID * HID];
    __shared__ ull sB1[HID];      // dup(log2e*(b1[jj] - sum_c W1[c][jj]))
    __shared__ ull sW2[HID];      // dup(W2[jj])  (final layer: NOT scaled)
    __shared__ float sB2;         // b2 - sum_j W2[j]

    const int tid = threadIdx.x;

    // ---- stage weights ----
    for (int i0 = tid; i0 < HID * HID; i0 += BLK) {
        // i0 = jj*32 + cc  ->  W1[cc*32 + jj]
        unsigned u = __float_as_uint(LOG2E * W1[((i0 & 31) << 5) | (i0 >> 5)]);
        sW1t[i0] = (ull)u | ((ull)u << 32);
    }
    for (int i0 = tid; i0 < HID * 8; i0 += BLK) {
        int jj = i0 >> 3, c = i0 & 7;
        float v = 0.0f;
        if (c < 5)       v = LOG2E * W0[c * HID + jj];
        else if (c == 5) v = LOG2E * b0[jj];
        unsigned u = __float_as_uint(v);
        sW0r[i0] = (ull)u | ((ull)u << 32);
    }
    if (tid < HID) {
        float s = 0.0f;
        for (int c = 0; c < HID; c++) s += W1[c * HID + tid];   // coalesced across tid
        unsigned u1 = __float_as_uint(LOG2E * (b1[tid] - s));
        unsigned u2 = __float_as_uint(W2[tid]);
        sB1[tid] = (ull)u1 | ((ull)u1 << 32);
        sW2[tid] = (ull)u2 | ((ull)u2 << 32);
    }
    if (tid == 0) {
        float s = 0.0f;
        for (int jj = 0; jj < HID; jj++) s += W2[jj];
        sB2 = b2[0] - s;
    }
    __syncthreads();

    const int gid = blockIdx.x * BLK + tid;
    const int base = gid * 4;
    const int t = base >> 16;
    const int p = base & (NPTS - 1);
    const float* xt = x + ((size_t)t << 16);
    const int i = p >> 8;
    const int j = p & 255;

    // Stencil (reference's exact wrap semantics)
    const float4 c4 = *reinterpret_cast<const float4*>(xt + p);
    const float4 u4 = *reinterpret_cast<const float4*>(xt + ((p - NSIDE) & (NPTS - 1)));
    const float4 d4 = *reinterpret_cast<const float4*>(xt + ((p + NSIDE) & (NPTS - 1)));
    const float lE = xt[(p - 1) & (NPTS - 1)];
    const float rE = xt[(i << 8) | ((j + 4) & 255)];

    // pair0 = points (0,1), pair1 = points (2,3); order: l, l2(up), c, r, r2(down)
    ull px0[5] = { pk2(lE,   c4.x), pk2(u4.x, u4.y), pk2(c4.x, c4.y),
                   pk2(c4.y, c4.z), pk2(d4.x, d4.y) };
    ull px1[5] = { pk2(c4.y, c4.z), pk2(u4.z, u4.w), pk2(c4.z, c4.w),
                   pk2(c4.w, rE),   pk2(d4.z, d4.w) };

    // ---- layer 0: [5] -> [32], g-activation ----
    ull h0a[HID], h0b[HID];
#pragma unroll
    for (int jj = 0; jj < HID; jj++) {
        const ulonglong2* row = reinterpret_cast<const ulonglong2*>(sW0r + jj * 8);
        ulonglong2 w01 = row[0];   // w0, w1
        ulonglong2 w23 = row[1];   // w2, w3
        ulonglong2 w4b = row[2];   // w4, b0
        ull a = w4b.y;
        ull b = a;
        a = fma2(px0[0], w01.x, a); b = fma2(px1[0], w01.x, b);
        a = fma2(px0[1], w01.y, a); b = fma2(px1[1], w01.y, b);
        a = fma2(px0[2], w23.x, a); b = fma2(px1[2], w23.x, b);
        a = fma2(px0[3], w23.y, a); b = fma2(px1[3], w23.y, b);
        a = fma2(px0[4], w4b.x, a); b = fma2(px1[4], w4b.x, b);
        h0a[jj] = g2(a);
        h0b[jj] = g2(b);
    }

    // ---- layer 1: [32] -> [32], g-activation, fused layer-2 accumulation ----
    ull oa = pk2(sB2, sB2);
    ull ob = oa;
#pragma unroll 2
    for (int jj = 0; jj < HID; jj++) {
        ull a = sB1[jj];
        ull b = a;
        const ulonglong2* row = reinterpret_cast<const ulonglong2*>(sW1t + jj * HID);
#pragma unroll
        for (int k = 0; k < HID / 2; k++) {
            ulonglong2 w = row[k];                 // weights for cc=2k, 2k+1
            a = fma2(h0a[2 * k],     w.x, a);
            b = fma2(h0b[2 * k],     w.x, b);
            a = fma2(h0a[2 * k + 1], w.y, a);
            b = fma2(h0b[2 * k + 1], w.y, b);
        }
        a = g2(a);
        b = g2(b);
        ull w2 = sW2[jj];
        oa = fma2(a, w2, oa);
        ob = fma2(b, w2, ob);
    }

    float o0, o1, o2, o3;
    upk2(oa, o0, o1);
    upk2(ob, o2, o3);
    *reinterpret_cast<float4*>(out + base) = make_float4(o0, o1, o2, o3);
}

extern "C" void kernel_launch(void* const* d_in, const int* in_sizes, int n_in,
                              void* d_out, int out_size) {
    const float* x  = (const float*)d_in[0];
    const float* W0 = (const float*)d_in[1];
    const float* b0 = (const float*)d_in[2];
    const float* W1 = (const float*)d_in[3];
    const float* b1 = (const float*)d_in[4];
    const float* W2 = (const float*)d_in[5];
    const float* b2 = (const float*)d_in[6];
    float* out = (float*)d_out;

    const int total = T_STEPS * NPTS;       // 4194304 points
    const int threads = total / 4;          // 4 points per thread
    mlpconv_kernel<<<threads / BLK, BLK>>>(x, W0, b0, W1, b1, W2, b2, out);
}